// round 5
// baseline (speedup 1.0000x reference)
#include <cuda_runtime.h>
#include <cuda_bf16.h>
#include <math.h>

// Problem constants
#define NB   64
#define ORD  2
#define SS   256
#define DD   256
#define NH   8
#define HDH  32   // head dim

// ---------------- scratch (device globals: allocation-free) ----------------
// XP[ic][b][s][d], ic = i*2+c
__device__ float g_XP[4L * NB * SS * DD];          // 16,777,216 floats (67 MB)
// H[b][i][t][d] = sum_c (attn + xproj + gbias)
__device__ float g_H[(long)NB * ORD * SS * DD];    // 8,388,608 floats (33 MB)
// per-head scores [ic][b][s][h]
__device__ float g_AS[4 * NB * SS * NH];
__device__ float g_AD[4 * NB * SS * NH];
// packed adjacency bitmasks [b][i][s][w], bit (t&31) of word t>>5
__device__ unsigned g_M1[NB * ORD * SS * (SS / 32)];
__device__ unsigned g_M2[NB * ORD * SS * (SS / 32)];

// ---------------- K1: projection GEMM  XP = x[:,i] @ W[i,c] + bp ----------------
// grid (2 ntile, 128 mtile, 4 ic), 256 threads, BM=BN=128, BK=16, 8x8 microtile
__global__ __launch_bounds__(256) void k_proj(const float* __restrict__ x,
                                              const float* __restrict__ Wp,
                                              const float* __restrict__ bp) {
    __shared__ float As[16][132];
    __shared__ float Bs[16][132];

    const int ic = blockIdx.z;
    const int i  = ic >> 1;
    const int ntile = blockIdx.x;        // 0..1
    const int mtile = blockIdx.y;        // 0..127
    const int tid = threadIdx.x;

    const int tx = tid & 15;             // n group
    const int ty = tid >> 4;             // m group

    const int row0 = mtile * 128;

    // loader indices
    const int aR  = tid >> 2;            // 0..63
    const int aK4 = (tid & 3) * 4;       // 0,4,8,12
    const int bK  = tid >> 5;            // 0..7
    const int bN4 = (tid & 31) * 4;      // 0..124

    const float* Wbase = Wp + (long)ic * 256 * 256 + ntile * 128;

    float acc[8][8];
#pragma unroll
    for (int a = 0; a < 8; a++)
#pragma unroll
        for (int b = 0; b < 8; b++) acc[a][b] = 0.f;

    for (int k0 = 0; k0 < 256; k0 += 16) {
        // A tile: rows of x (flattened b*256+s), transposed into As[k][m]
#pragma unroll
        for (int rr = 0; rr < 2; rr++) {
            int row = row0 + aR + rr * 64;
            int b = row >> 8, s = row & 255;
            const float4 av = *(const float4*)(x + ((long)((b * 2 + i) * 256 + s)) * 256 + k0 + aK4);
            As[aK4 + 0][aR + rr * 64] = av.x;
            As[aK4 + 1][aR + rr * 64] = av.y;
            As[aK4 + 2][aR + rr * 64] = av.z;
            As[aK4 + 3][aR + rr * 64] = av.w;
        }
        // B tile
#pragma unroll
        for (int rr = 0; rr < 2; rr++) {
            int k = bK + rr * 8;
            *(float4*)&Bs[k][bN4] = *(const float4*)(Wbase + (long)(k0 + k) * 256 + bN4);
        }
        __syncthreads();

#pragma unroll
        for (int kk = 0; kk < 16; kk++) {
            float af[8], bf[8];
            *(float4*)(af)     = *(const float4*)&As[kk][ty * 8];
            *(float4*)(af + 4) = *(const float4*)&As[kk][ty * 8 + 4];
            *(float4*)(bf)     = *(const float4*)&Bs[kk][tx * 8];
            *(float4*)(bf + 4) = *(const float4*)&Bs[kk][tx * 8 + 4];
#pragma unroll
            for (int mi = 0; mi < 8; mi++)
#pragma unroll
                for (int ni = 0; ni < 8; ni++)
                    acc[mi][ni] = fmaf(af[mi], bf[ni], acc[mi][ni]);
        }
        __syncthreads();
    }

    // epilogue: add bias, write XP
    float bv[8];
#pragma unroll
    for (int j = 0; j < 8; j++) bv[j] = bp[ic * 256 + ntile * 128 + tx * 8 + j];

#pragma unroll
    for (int mi = 0; mi < 8; mi++) {
        int row = row0 + ty * 8 + mi;
        float* dst = g_XP + ((long)ic * 16384 + row) * 256 + ntile * 128 + tx * 8;
        float4 o0, o1;
        o0.x = acc[mi][0] + bv[0]; o0.y = acc[mi][1] + bv[1];
        o0.z = acc[mi][2] + bv[2]; o0.w = acc[mi][3] + bv[3];
        o1.x = acc[mi][4] + bv[4]; o1.y = acc[mi][5] + bv[5];
        o1.z = acc[mi][6] + bv[6]; o1.w = acc[mi][7] + bv[7];
        *(float4*)(dst)     = o0;
        *(float4*)(dst + 4) = o1;
    }
}

// ---------------- K2a: per-head src/dst scores ----------------
// grid (256 s, 64 b, 4 ic), 256 threads (tid = d); warp w reduces head w
__global__ __launch_bounds__(256) void k_scores(const float* __restrict__ att_src,
                                                const float* __restrict__ att_dst) {
    const int s = blockIdx.x, b = blockIdx.y, ic = blockIdx.z;
    const int tid = threadIdx.x;
    const int lane = tid & 31, w = tid >> 5;

    float v = g_XP[((long)(ic * 64 + b) * 256 + s) * 256 + tid];
    float ps = v * att_src[ic * 256 + tid];
    float pd = v * att_dst[ic * 256 + tid];
#pragma unroll
    for (int o = 16; o; o >>= 1) {
        ps += __shfl_xor_sync(0xffffffffu, ps, o);
        pd += __shfl_xor_sync(0xffffffffu, pd, o);
    }
    if (lane == 0) {
        long base = ((long)(ic * 64 + b) * 256 + s) * 8 + w;
        g_AS[base] = ps;
        g_AD[base] = pd;
    }
}

// ---------------- K2b: packed adjacency masks ----------------
// grid (256 s, 2 i, 64 b), 256 threads (tid = t)
__global__ __launch_bounds__(256) void k_masks(const int* __restrict__ A) {
    const int s = blockIdx.x, i = blockIdx.y, b = blockIdx.z;
    const int t = threadIdx.x;
    const int lane = t & 31, w = t >> 5;
    int v = A[((long)((b * 2 + i) * 256 + s)) * 256 + t];
    unsigned m1 = __ballot_sync(0xffffffffu, (v == 2) | (v == 4));
    unsigned m2 = __ballot_sync(0xffffffffu, (v == 3) | (v == 4));
    if (lane == 0) {
        long base = ((long)((b * 2 + i) * 256 + s)) * 8 + w;
        g_M1[base] = m1;
        g_M2[base] = m2;
    }
}

// ---------------- K3: masked softmax attention + residual, both convs ----------------
// grid (8 h, 2 i, 64 b), 256 threads
// thread roles:
//   softmax-column role: thread tid owns dest column t=tid (max, exp, denom)
//   accumulate role: tx=tid&63 owns t in [4tx,4tx+4), ty=tid>>6 owns d in [8ty,8ty+8)
__global__ __launch_bounds__(256) void k_attn(const float* __restrict__ gbias) {
    __shared__ float    Vsm[128 * 32];    // 16 KB : current 128-source half of xh slice
    __shared__ float    Psm[16 * 256];    // 16 KB : unnormalized exp chunk [ss][t]
    __shared__ unsigned msk[256 * 8];     // 8 KB
    __shared__ float    as_sm[256];
    __shared__ float    ad_sm[256];
    __shared__ float    dinv_sm[256];

    const int h = blockIdx.x, i = blockIdx.y, b = blockIdx.z;
    const int tid = threadIdx.x;
    const int tx = tid & 63, ty = tid >> 6;
    const int wq = tid >> 5;            // mask word for column tid
    const int sh = tid & 31;            // bit within word

    float accP[4][8];                   // persistent across convs
#pragma unroll
    for (int a = 0; a < 4; a++)
#pragma unroll
        for (int d = 0; d < 8; d++) accP[a][d] = 0.f;

    for (int c = 0; c < 2; c++) {
        const int ic = i * 2 + c;
        const long xpbase = ((long)(ic * 64 + b) * 256) * 256;   // + s*256 + d
        __syncthreads();   // protect smem from previous conv's readers

        // load mask (conv0 -> A1, conv1 -> A2), scores
        {
            const unsigned* gm = (c == 0 ? g_M1 : g_M2) + ((long)((b * 2 + i) * 256)) * 8;
#pragma unroll
            for (int j = 0; j < 8; j++) msk[tid + 256 * j] = gm[tid + 256 * j];
            long sbase = ((long)(ic * 64 + b) * 256 + tid) * 8 + h;
            as_sm[tid] = g_AS[sbase];
            ad_sm[tid] = g_AD[sbase];
        }
        __syncthreads();

        // phase A: column max over all 256 sources (masked entries -> logit 0)
        const float ad = ad_sm[tid];
        float m = -1e30f;
#pragma unroll 8
        for (int s = 0; s < 256; s++) {
            unsigned bit = (msk[s * 8 + wq] >> sh) & 1u;
            float raw = as_sm[s] + ad;
            float v = fmaxf(raw, 0.2f * raw);     // leaky_relu(0.2)
            float l = bit ? v : 0.f;
            m = fmaxf(m, l);
        }

        float dlocal = 0.f;
        float acc[4][8];
#pragma unroll
        for (int a = 0; a < 4; a++)
#pragma unroll
            for (int d = 0; d < 8; d++) acc[a][d] = 0.f;

        for (int half = 0; half < 2; half++) {
            __syncthreads();
            // load V half: xh[s, h*32 + d] for s in [half*128, half*128+128)
#pragma unroll
            for (int j = 0; j < 4; j++) {
                int f = tid + 256 * j;            // 0..1023 float4s
                int sl = f >> 3, d4 = (f & 7) * 4;
                int s = half * 128 + sl;
                *(float4*)&Vsm[sl * 32 + d4] =
                    *(const float4*)(g_XP + xpbase + (long)s * 256 + h * 32 + d4);
            }
            __syncthreads();

            for (int sc = 0; sc < 8; sc++) {
                const int sbase = half * 128 + sc * 16;
                // P generation: thread owns column t=tid
#pragma unroll
                for (int ss = 0; ss < 16; ss++) {
                    int s = sbase + ss;
                    unsigned bit = (msk[s * 8 + wq] >> sh) & 1u;
                    float raw = as_sm[s] + ad;
                    float v = fmaxf(raw, 0.2f * raw);
                    float l = bit ? v : 0.f;
                    float e = __expf(l - m);
                    Psm[ss * 256 + tid] = e;
                    dlocal += e;
                }
                __syncthreads();
                // accumulate: acc[tt][dd] += P[s][t] * V[s][d]
#pragma unroll
                for (int ss = 0; ss < 16; ss++) {
                    float4 p4 = *(const float4*)&Psm[ss * 256 + tx * 4];
                    int sl = sc * 16 + ss;
                    float4 v0 = *(const float4*)&Vsm[sl * 32 + ty * 8];
                    float4 v1 = *(const float4*)&Vsm[sl * 32 + ty * 8 + 4];
                    float pv[4] = {p4.x, p4.y, p4.z, p4.w};
                    float vv[8] = {v0.x, v0.y, v0.z, v0.w, v1.x, v1.y, v1.z, v1.w};
#pragma unroll
                    for (int a = 0; a < 4; a++)
#pragma unroll
                        for (int d = 0; d < 8; d++)
                            acc[a][d] = fmaf(pv[a], vv[d], acc[a][d]);
                }
                __syncthreads();
            }
        }

        // denominators to smem, then epilogue: accP += acc/denom + xproj + gbias
        dinv_sm[tid] = 1.f / dlocal;
        __syncthreads();

        float gb[8];
#pragma unroll
        for (int d = 0; d < 8; d++) gb[d] = gbias[ic * 256 + h * 32 + ty * 8 + d];

#pragma unroll
        for (int a = 0; a < 4; a++) {
            int t = tx * 4 + a;
            float di = dinv_sm[t];
            const float* xpp = g_XP + xpbase + (long)t * 256 + h * 32 + ty * 8;
            float4 x0 = *(const float4*)(xpp);
            float4 x1 = *(const float4*)(xpp + 4);
            float xv[8] = {x0.x, x0.y, x0.z, x0.w, x1.x, x1.y, x1.z, x1.w};
#pragma unroll
            for (int d = 0; d < 8; d++)
                accP[a][d] += acc[a][d] * di + xv[d] + gb[d];
        }
    }

    // write H[b][i][t][d_slice]
#pragma unroll
    for (int a = 0; a < 4; a++) {
        int t = tx * 4 + a;
        float* dst = g_H + ((long)((b * 2 + i) * 256 + t)) * 256 + h * 32 + ty * 8;
        float4 o0, o1;
        o0.x = accP[a][0]; o0.y = accP[a][1]; o0.z = accP[a][2]; o0.w = accP[a][3];
        o1.x = accP[a][4]; o1.y = accP[a][5]; o1.z = accP[a][6]; o1.w = accP[a][7];
        *(float4*)(dst)     = o0;
        *(float4*)(dst + 4) = o1;
    }
}

// ---------------- K4: cross-order mean + PReLU ----------------
// one thread per (b,t,d), writes both orders
__global__ __launch_bounds__(256) void k_final(const float* __restrict__ prelu_a,
                                               float* __restrict__ out) {
    int idx = blockIdx.x * 256 + threadIdx.x;   // 0 .. 64*256*256-1
    int d = idx & 255;
    int t = (idx >> 8) & 255;
    int b = idx >> 16;
    long i0 = ((long)((b * 2 + 0) * 256 + t)) * 256 + d;
    long i1 = ((long)((b * 2 + 1) * 256 + t)) * 256 + d;
    float h0 = g_H[i0], h1 = g_H[i1];
    float mn = 0.5f * (h0 + h1);
    float a = prelu_a[d];
    float o0 = h0 + mn, o1 = h1 + mn;
    out[i0] = (o0 >= 0.f) ? o0 : a * o0;
    out[i1] = (o1 >= 0.f) ? o1 : a * o1;
}

// ---------------- launch ----------------
extern "C" void kernel_launch(void* const* d_in, const int* in_sizes, int n_in,
                              void* d_out, int out_size) {
    const float* x        = (const float*)d_in[0];
    const int*   A        = (const int*)d_in[1];
    const float* Wp       = (const float*)d_in[2];
    const float* bp       = (const float*)d_in[3];
    const float* att_src  = (const float*)d_in[4];
    const float* att_dst  = (const float*)d_in[5];
    const float* gbias    = (const float*)d_in[6];
    const float* prelu_a  = (const float*)d_in[7];
    float* out = (float*)d_out;

    k_proj  <<<dim3(2, 128, 4), 256>>>(x, Wp, bp);
    k_scores<<<dim3(256, 64, 4), 256>>>(att_src, att_dst);
    k_masks <<<dim3(256, 2, 64), 256>>>(A);
    k_attn  <<<dim3(8, 2, 64), 256>>>(gbias);
    k_final <<<16384, 256>>>(prelu_a, out);
}

// round 7
// speedup vs baseline: 1.1403x; 1.1403x over previous
#include <cuda_runtime.h>
#include <cuda_bf16.h>
#include <cstdint>
#include <math.h>

// Problem constants
#define NB   64
#define ORD  2
#define SS   256
#define DD   256
#define NH   8
#define HDH  32   // head dim

// ---------------- scratch (device globals: allocation-free) ----------------
__device__ float g_XP[4L * NB * SS * DD];          // XP[ic][row][d]
__device__ float g_H[(long)NB * ORD * SS * DD];
__device__ float g_AS[4 * NB * SS * NH];
__device__ float g_AD[4 * NB * SS * NH];
__device__ unsigned g_M1[NB * ORD * SS * (SS / 32)];
__device__ unsigned g_M2[NB * ORD * SS * (SS / 32)];

// ---------------- mma.sync helpers (portable sm_80+ PTX; safe on compute_103) ----
__device__ __forceinline__ void mma16816(float* d, const uint32_t* a,
                                         const uint32_t* b, const float* c) {
    asm volatile(
        "mma.sync.aligned.m16n8k16.row.col.f32.bf16.bf16.f32 "
        "{%0,%1,%2,%3}, {%4,%5,%6,%7}, {%8,%9}, {%10,%11,%12,%13};"
        : "=f"(d[0]), "=f"(d[1]), "=f"(d[2]), "=f"(d[3])
        : "r"(a[0]), "r"(a[1]), "r"(a[2]), "r"(a[3]),
          "r"(b[0]), "r"(b[1]),
          "f"(c[0]), "f"(c[1]), "f"(c[2]), "f"(c[3]));
}

__device__ __forceinline__ void split2(float a, float b, uint32_t& h, uint32_t& l) {
    __nv_bfloat162 hb = __floats2bfloat162_rn(a, b);
    float ra = a - __bfloat162float(hb.x);
    float rb = b - __bfloat162float(hb.y);
    __nv_bfloat162 lb = __floats2bfloat162_rn(ra, rb);
    h = *reinterpret_cast<uint32_t*>(&hb);
    l = *reinterpret_cast<uint32_t*>(&lb);
}

// ---------------- K1: mma.sync split-bf16 projection GEMM ----------------
// XP[ic] = x[:,i] @ W[ic] + bp[ic]
// grid (2 ntile, 128 mtile, 4 ic), 256 threads, BM=128 BN=128 BK=32
// warps: 4(m) x 2(n); warp tile 32 x 64; atoms m16n8k16, 3 split-precision terms
#define APITCH 40   // bf16 elements per smem row (32 data + 8 pad)
__global__ __launch_bounds__(256) void k_proj_mma(const float* __restrict__ x,
                                                  const float* __restrict__ Wp,
                                                  const float* __restrict__ bp) {
    __shared__ uint16_t Ahi[128 * APITCH];
    __shared__ uint16_t Alo[128 * APITCH];
    __shared__ uint16_t Bhi[128 * APITCH];
    __shared__ uint16_t Blo[128 * APITCH];
    __shared__ float    bias_sm[128];

    const int tid = threadIdx.x;
    const int lane = tid & 31, wid = tid >> 5;
    const int wm = wid & 3, wn = wid >> 2;
    const int g = lane >> 2, tg = lane & 3;

    const int ntile = blockIdx.x;     // 0..1
    const int mtile = blockIdx.y;     // 0..127
    const int ic = blockIdx.z, i = ic >> 1;

    // staging roles: thread owns one smem row (r = tid>>1) and one 16-col half
    const int sr = tid >> 1;
    const int kh = (tid & 1) * 16;

    // A source row
    {
        if (tid < 128) bias_sm[tid] = bp[ic * 256 + ntile * 128 + tid];
    }
    const int grow = mtile * 128 + sr;
    const int gb_ = grow >> 8, gs = grow & 255;
    const float* arow = x + ((long)((gb_ * 2 + i) * 256 + gs)) * 256;
    const int ncol = ntile * 128 + sr;            // B: global output column
    const float* wcolbase = Wp + (long)ic * 65536 + ncol;

    float acc[2][8][4];
#pragma unroll
    for (int mi = 0; mi < 2; mi++)
#pragma unroll
        for (int ni = 0; ni < 8; ni++)
#pragma unroll
            for (int q = 0; q < 4; q++) acc[mi][ni][q] = 0.f;

    for (int k0 = 0; k0 < 256; k0 += 32) {
        // ---- stage A [128 x 32] fp32 -> hi/lo bf16 ----
        {
            float4 f0 = *(const float4*)(arow + k0 + kh);
            float4 f1 = *(const float4*)(arow + k0 + kh + 4);
            float4 f2 = *(const float4*)(arow + k0 + kh + 8);
            float4 f3 = *(const float4*)(arow + k0 + kh + 12);
            uint4 h0, l0, h1, l1;
            split2(f0.x, f0.y, h0.x, l0.x); split2(f0.z, f0.w, h0.y, l0.y);
            split2(f1.x, f1.y, h0.z, l0.z); split2(f1.z, f1.w, h0.w, l0.w);
            split2(f2.x, f2.y, h1.x, l1.x); split2(f2.z, f2.w, h1.y, l1.y);
            split2(f3.x, f3.y, h1.z, l1.z); split2(f3.z, f3.w, h1.w, l1.w);
            uint16_t* pa = &Ahi[sr * APITCH + kh];
            uint16_t* pl = &Alo[sr * APITCH + kh];
            *(uint4*)(pa) = h0; *(uint4*)(pa + 8) = h1;
            *(uint4*)(pl) = l0; *(uint4*)(pl + 8) = l1;
        }
        // ---- stage B: Bs[n][kk] = W[k0+kk][n] ----
        {
            float f[16];
#pragma unroll
            for (int t = 0; t < 16; t++) f[t] = wcolbase[(long)(k0 + kh + t) * 256];
            uint4 h0, l0, h1, l1;
            split2(f[0], f[1], h0.x, l0.x);  split2(f[2], f[3], h0.y, l0.y);
            split2(f[4], f[5], h0.z, l0.z);  split2(f[6], f[7], h0.w, l0.w);
            split2(f[8], f[9], h1.x, l1.x);  split2(f[10], f[11], h1.y, l1.y);
            split2(f[12], f[13], h1.z, l1.z); split2(f[14], f[15], h1.w, l1.w);
            uint16_t* pb = &Bhi[sr * APITCH + kh];
            uint16_t* pl = &Blo[sr * APITCH + kh];
            *(uint4*)(pb) = h0; *(uint4*)(pb + 8) = h1;
            *(uint4*)(pl) = l0; *(uint4*)(pl + 8) = l1;
        }
        __syncthreads();

        // ---- compute: 2 k-atoms x (2 m x 8 n) x 3 terms ----
#pragma unroll
        for (int ka = 0; ka < 32; ka += 16) {
            uint32_t ah[2][4], al[2][4];
            const int c0 = ka + tg * 2;
#pragma unroll
            for (int mi = 0; mi < 2; mi++) {
                const int r0 = wm * 32 + mi * 16 + g;
                ah[mi][0] = *(const uint32_t*)&Ahi[r0 * APITCH + c0];
                ah[mi][1] = *(const uint32_t*)&Ahi[(r0 + 8) * APITCH + c0];
                ah[mi][2] = *(const uint32_t*)&Ahi[r0 * APITCH + c0 + 8];
                ah[mi][3] = *(const uint32_t*)&Ahi[(r0 + 8) * APITCH + c0 + 8];
                al[mi][0] = *(const uint32_t*)&Alo[r0 * APITCH + c0];
                al[mi][1] = *(const uint32_t*)&Alo[(r0 + 8) * APITCH + c0];
                al[mi][2] = *(const uint32_t*)&Alo[r0 * APITCH + c0 + 8];
                al[mi][3] = *(const uint32_t*)&Alo[(r0 + 8) * APITCH + c0 + 8];
            }
#pragma unroll
            for (int ni = 0; ni < 8; ni++) {
                const int n = wn * 64 + ni * 8 + g;
                uint32_t bh[2], bl[2];
                bh[0] = *(const uint32_t*)&Bhi[n * APITCH + c0];
                bh[1] = *(const uint32_t*)&Bhi[n * APITCH + c0 + 8];
                bl[0] = *(const uint32_t*)&Blo[n * APITCH + c0];
                bl[1] = *(const uint32_t*)&Blo[n * APITCH + c0 + 8];
#pragma unroll
                for (int mi = 0; mi < 2; mi++) {
                    mma16816(acc[mi][ni], ah[mi], bh, acc[mi][ni]);
                    mma16816(acc[mi][ni], al[mi], bh, acc[mi][ni]);
                    mma16816(acc[mi][ni], ah[mi], bl, acc[mi][ni]);
                }
            }
        }
        __syncthreads();
    }

    // ---- epilogue: add bias, write XP ----
#pragma unroll
    for (int mi = 0; mi < 2; mi++) {
        const int r0 = mtile * 128 + wm * 32 + mi * 16 + g;
#pragma unroll
        for (int ni = 0; ni < 8; ni++) {
            const int cl = wn * 64 + ni * 8 + tg * 2;        // local col
            const int cgl = ntile * 128 + cl;                // global col
            float b0 = bias_sm[cl], b1 = bias_sm[cl + 1];
            float2 o0 = make_float2(acc[mi][ni][0] + b0, acc[mi][ni][1] + b1);
            float2 o1 = make_float2(acc[mi][ni][2] + b0, acc[mi][ni][3] + b1);
            *(float2*)(g_XP + ((long)ic * 16384 + r0) * 256 + cgl) = o0;
            *(float2*)(g_XP + ((long)ic * 16384 + r0 + 8) * 256 + cgl) = o1;
        }
    }
}

// ---------------- K2a: per-head src/dst scores ----------------
__global__ __launch_bounds__(256) void k_scores(const float* __restrict__ att_src,
                                                const float* __restrict__ att_dst) {
    const int s = blockIdx.x, b = blockIdx.y, ic = blockIdx.z;
    const int tid = threadIdx.x;
    const int lane = tid & 31, w = tid >> 5;

    float v = g_XP[((long)(ic * 64 + b) * 256 + s) * 256 + tid];
    float ps = v * att_src[ic * 256 + tid];
    float pd = v * att_dst[ic * 256 + tid];
#pragma unroll
    for (int o = 16; o; o >>= 1) {
        ps += __shfl_xor_sync(0xffffffffu, ps, o);
        pd += __shfl_xor_sync(0xffffffffu, pd, o);
    }
    if (lane == 0) {
        long base = ((long)(ic * 64 + b) * 256 + s) * 8 + w;
        g_AS[base] = ps;
        g_AD[base] = pd;
    }
}

// ---------------- K2b: packed adjacency masks ----------------
__global__ __launch_bounds__(256) void k_masks(const int* __restrict__ A) {
    const int s = blockIdx.x, i = blockIdx.y, b = blockIdx.z;
    const int t = threadIdx.x;
    const int lane = t & 31, w = t >> 5;
    int v = A[((long)((b * 2 + i) * 256 + s)) * 256 + t];
    unsigned m1 = __ballot_sync(0xffffffffu, (v == 2) | (v == 4));
    unsigned m2 = __ballot_sync(0xffffffffu, (v == 3) | (v == 4));
    if (lane == 0) {
        long base = ((long)((b * 2 + i) * 256 + s)) * 8 + w;
        g_M1[base] = m1;
        g_M2[base] = m2;
    }
}

// ---------------- K3: masked softmax attention + residual, both convs ----------------
__global__ __launch_bounds__(256) void k_attn(const float* __restrict__ gbias) {
    __shared__ float    Vsm[128 * 32];
    __shared__ float    Psm[16 * 256];
    __shared__ unsigned msk[256 * 8];
    __shared__ float    as_sm[256];
    __shared__ float    ad_sm[256];
    __shared__ float    dinv_sm[256];

    const int h = blockIdx.x, i = blockIdx.y, b = blockIdx.z;
    const int tid = threadIdx.x;
    const int tx = tid & 63, ty = tid >> 6;
    const int wq = tid >> 5;
    const int sh = tid & 31;

    float accP[4][8];
#pragma unroll
    for (int a = 0; a < 4; a++)
#pragma unroll
        for (int d = 0; d < 8; d++) accP[a][d] = 0.f;

    for (int c = 0; c < 2; c++) {
        const int ic = i * 2 + c;
        const long xpbase = ((long)(ic * 64 + b) * 256) * 256;
        __syncthreads();

        {
            const unsigned* gm = (c == 0 ? g_M1 : g_M2) + ((long)((b * 2 + i) * 256)) * 8;
#pragma unroll
            for (int j = 0; j < 8; j++) msk[tid + 256 * j] = gm[tid + 256 * j];
            long sbase = ((long)(ic * 64 + b) * 256 + tid) * 8 + h;
            as_sm[tid] = g_AS[sbase];
            ad_sm[tid] = g_AD[sbase];
        }
        __syncthreads();

        const float ad = ad_sm[tid];
        float m = -1e30f;
#pragma unroll 8
        for (int s = 0; s < 256; s++) {
            unsigned bit = (msk[s * 8 + wq] >> sh) & 1u;
            float raw = as_sm[s] + ad;
            float v = fmaxf(raw, 0.2f * raw);
            float l = bit ? v : 0.f;
            m = fmaxf(m, l);
        }

        float dlocal = 0.f;
        float acc[4][8];
#pragma unroll
        for (int a = 0; a < 4; a++)
#pragma unroll
            for (int d = 0; d < 8; d++) acc[a][d] = 0.f;

        for (int half = 0; half < 2; half++) {
            __syncthreads();
#pragma unroll
            for (int j = 0; j < 4; j++) {
                int f = tid + 256 * j;
                int sl = f >> 3, d4 = (f & 7) * 4;
                int s = half * 128 + sl;
                *(float4*)&Vsm[sl * 32 + d4] =
                    *(const float4*)(g_XP + xpbase + (long)s * 256 + h * 32 + d4);
            }
            __syncthreads();

            for (int sc = 0; sc < 8; sc++) {
                const int sbase = half * 128 + sc * 16;
#pragma unroll
                for (int ss = 0; ss < 16; ss++) {
                    int s = sbase + ss;
                    unsigned bit = (msk[s * 8 + wq] >> sh) & 1u;
                    float raw = as_sm[s] + ad;
                    float v = fmaxf(raw, 0.2f * raw);
                    float l = bit ? v : 0.f;
                    float e = __expf(l - m);
                    Psm[ss * 256 + tid] = e;
                    dlocal += e;
                }
                __syncthreads();
#pragma unroll
                for (int ss = 0; ss < 16; ss++) {
                    float4 p4 = *(const float4*)&Psm[ss * 256 + tx * 4];
                    int sl = sc * 16 + ss;
                    float4 v0 = *(const float4*)&Vsm[sl * 32 + ty * 8];
                    float4 v1 = *(const float4*)&Vsm[sl * 32 + ty * 8 + 4];
                    float pv[4] = {p4.x, p4.y, p4.z, p4.w};
                    float vv[8] = {v0.x, v0.y, v0.z, v0.w, v1.x, v1.y, v1.z, v1.w};
#pragma unroll
                    for (int a = 0; a < 4; a++)
#pragma unroll
                        for (int d = 0; d < 8; d++)
                            acc[a][d] = fmaf(pv[a], vv[d], acc[a][d]);
                }
                __syncthreads();
            }
        }

        dinv_sm[tid] = 1.f / dlocal;
        __syncthreads();

        float gb[8];
#pragma unroll
        for (int d = 0; d < 8; d++) gb[d] = gbias[ic * 256 + h * 32 + ty * 8 + d];

#pragma unroll
        for (int a = 0; a < 4; a++) {
            int t = tx * 4 + a;
            float di = dinv_sm[t];
            const float* xpp = g_XP + xpbase + (long)t * 256 + h * 32 + ty * 8;
            float4 x0 = *(const float4*)(xpp);
            float4 x1 = *(const float4*)(xpp + 4);
            float xv[8] = {x0.x, x0.y, x0.z, x0.w, x1.x, x1.y, x1.z, x1.w};
#pragma unroll
            for (int d = 0; d < 8; d++)
                accP[a][d] += acc[a][d] * di + xv[d] + gb[d];
        }
    }

#pragma unroll
    for (int a = 0; a < 4; a++) {
        int t = tx * 4 + a;
        float* dst = g_H + ((long)((b * 2 + i) * 256 + t)) * 256 + h * 32 + ty * 8;
        float4 o0, o1;
        o0.x = accP[a][0]; o0.y = accP[a][1]; o0.z = accP[a][2]; o0.w = accP[a][3];
        o1.x = accP[a][4]; o1.y = accP[a][5]; o1.z = accP[a][6]; o1.w = accP[a][7];
        *(float4*)(dst)     = o0;
        *(float4*)(dst + 4) = o1;
    }
}

// ---------------- K4: cross-order mean + PReLU ----------------
__global__ __launch_bounds__(256) void k_final(const float* __restrict__ prelu_a,
                                               float* __restrict__ out) {
    int idx = blockIdx.x * 256 + threadIdx.x;
    int d = idx & 255;
    int t = (idx >> 8) & 255;
    int b = idx >> 16;
    long i0 = ((long)((b * 2 + 0) * 256 + t)) * 256 + d;
    long i1 = ((long)((b * 2 + 1) * 256 + t)) * 256 + d;
    float h0 = g_H[i0], h1 = g_H[i1];
    float mn = 0.5f * (h0 + h1);
    float a = prelu_a[d];
    float o0 = h0 + mn, o1 = h1 + mn;
    out[i0] = (o0 >= 0.f) ? o0 : a * o0;
    out[i1] = (o1 >= 0.f) ? o1 : a * o1;
}

// ---------------- launch ----------------
extern "C" void kernel_launch(void* const* d_in, const int* in_sizes, int n_in,
                              void* d_out, int out_size) {
    const float* x        = (const float*)d_in[0];
    const int*   A        = (const int*)d_in[1];
    const float* Wp       = (const float*)d_in[2];
    const float* bp       = (const float*)d_in[3];
    const float* att_src  = (const float*)d_in[4];
    const float* att_dst  = (const float*)d_in[5];
    const float* gbias    = (const float*)d_in[6];
    const float* prelu_a  = (const float*)d_in[7];
    float* out = (float*)d_out;

    k_proj_mma<<<dim3(2, 128, 4), 256>>>(x, Wp, bp);
    k_scores  <<<dim3(256, 64, 4), 256>>>(att_src, att_dst);
    k_masks   <<<dim3(256, 2, 64), 256>>>(A);
    k_attn    <<<dim3(8, 2, 64), 256>>>(gbias);
    k_final   <<<16384, 256>>>(prelu_a, out);
}

// round 8
// speedup vs baseline: 1.4105x; 1.2370x over previous
#include <cuda_runtime.h>
#include <cuda_bf16.h>
#include <cstdint>
#include <math.h>

// Problem constants
#define NB   64
#define ORD  2
#define SS   256
#define DD   256
#define NH   8
#define HDH  32   // head dim

// ---------------- scratch (device globals: allocation-free) ----------------
__device__ float g_XP[4L * NB * SS * DD];          // XP[ic][row][d]
__device__ float g_H[(long)NB * ORD * SS * DD];
__device__ float g_AS[4 * NB * SS * NH];
__device__ float g_AD[4 * NB * SS * NH];
__device__ unsigned g_M1[NB * ORD * SS * (SS / 32)];
__device__ unsigned g_M2[NB * ORD * SS * (SS / 32)];

// ---------------- mma.sync helpers (portable sm_80+ PTX; safe on compute_103) ----
__device__ __forceinline__ void mma16816(float* d, const uint32_t* a,
                                         const uint32_t* b, const float* c) {
    asm volatile(
        "mma.sync.aligned.m16n8k16.row.col.f32.bf16.bf16.f32 "
        "{%0,%1,%2,%3}, {%4,%5,%6,%7}, {%8,%9}, {%10,%11,%12,%13};"
        : "=f"(d[0]), "=f"(d[1]), "=f"(d[2]), "=f"(d[3])
        : "r"(a[0]), "r"(a[1]), "r"(a[2]), "r"(a[3]),
          "r"(b[0]), "r"(b[1]),
          "f"(c[0]), "f"(c[1]), "f"(c[2]), "f"(c[3]));
}

__device__ __forceinline__ void split2(float a, float b, uint32_t& h, uint32_t& l) {
    __nv_bfloat162 hb = __floats2bfloat162_rn(a, b);
    float ra = a - __bfloat162float(hb.x);
    float rb = b - __bfloat162float(hb.y);
    __nv_bfloat162 lb = __floats2bfloat162_rn(ra, rb);
    h = *reinterpret_cast<uint32_t*>(&hb);
    l = *reinterpret_cast<uint32_t*>(&lb);
}

// ---------------- K1: mma.sync split-bf16 projection GEMM ----------------
#define APITCH 40   // bf16 elements per smem row (32 data + 8 pad)
__global__ __launch_bounds__(256) void k_proj_mma(const float* __restrict__ x,
                                                  const float* __restrict__ Wp,
                                                  const float* __restrict__ bp) {
    __shared__ uint16_t Ahi[128 * APITCH];
    __shared__ uint16_t Alo[128 * APITCH];
    __shared__ uint16_t Bhi[128 * APITCH];
    __shared__ uint16_t Blo[128 * APITCH];
    __shared__ float    bias_sm[128];

    const int tid = threadIdx.x;
    const int lane = tid & 31, wid = tid >> 5;
    const int wm = wid & 3, wn = wid >> 2;
    const int g = lane >> 2, tg = lane & 3;

    const int ntile = blockIdx.x;
    const int mtile = blockIdx.y;
    const int ic = blockIdx.z, i = ic >> 1;

    const int sr = tid >> 1;
    const int kh = (tid & 1) * 16;

    if (tid < 128) bias_sm[tid] = bp[ic * 256 + ntile * 128 + tid];

    const int grow = mtile * 128 + sr;
    const int gb_ = grow >> 8, gs = grow & 255;
    const float* arow = x + ((long)((gb_ * 2 + i) * 256 + gs)) * 256;
    const int ncol = ntile * 128 + sr;
    const float* wcolbase = Wp + (long)ic * 65536 + ncol;

    float acc[2][8][4];
#pragma unroll
    for (int mi = 0; mi < 2; mi++)
#pragma unroll
        for (int ni = 0; ni < 8; ni++)
#pragma unroll
            for (int q = 0; q < 4; q++) acc[mi][ni][q] = 0.f;

    for (int k0 = 0; k0 < 256; k0 += 32) {
        {
            float4 f0 = *(const float4*)(arow + k0 + kh);
            float4 f1 = *(const float4*)(arow + k0 + kh + 4);
            float4 f2 = *(const float4*)(arow + k0 + kh + 8);
            float4 f3 = *(const float4*)(arow + k0 + kh + 12);
            uint4 h0, l0, h1, l1;
            split2(f0.x, f0.y, h0.x, l0.x); split2(f0.z, f0.w, h0.y, l0.y);
            split2(f1.x, f1.y, h0.z, l0.z); split2(f1.z, f1.w, h0.w, l0.w);
            split2(f2.x, f2.y, h1.x, l1.x); split2(f2.z, f2.w, h1.y, l1.y);
            split2(f3.x, f3.y, h1.z, l1.z); split2(f3.z, f3.w, h1.w, l1.w);
            uint16_t* pa = &Ahi[sr * APITCH + kh];
            uint16_t* pl = &Alo[sr * APITCH + kh];
            *(uint4*)(pa) = h0; *(uint4*)(pa + 8) = h1;
            *(uint4*)(pl) = l0; *(uint4*)(pl + 8) = l1;
        }
        {
            float f[16];
#pragma unroll
            for (int t = 0; t < 16; t++) f[t] = wcolbase[(long)(k0 + kh + t) * 256];
            uint4 h0, l0, h1, l1;
            split2(f[0], f[1], h0.x, l0.x);  split2(f[2], f[3], h0.y, l0.y);
            split2(f[4], f[5], h0.z, l0.z);  split2(f[6], f[7], h0.w, l0.w);
            split2(f[8], f[9], h1.x, l1.x);  split2(f[10], f[11], h1.y, l1.y);
            split2(f[12], f[13], h1.z, l1.z); split2(f[14], f[15], h1.w, l1.w);
            uint16_t* pb = &Bhi[sr * APITCH + kh];
            uint16_t* pl = &Blo[sr * APITCH + kh];
            *(uint4*)(pb) = h0; *(uint4*)(pb + 8) = h1;
            *(uint4*)(pl) = l0; *(uint4*)(pl + 8) = l1;
        }
        __syncthreads();

#pragma unroll
        for (int ka = 0; ka < 32; ka += 16) {
            uint32_t ah[2][4], al[2][4];
            const int c0 = ka + tg * 2;
#pragma unroll
            for (int mi = 0; mi < 2; mi++) {
                const int r0 = wm * 32 + mi * 16 + g;
                ah[mi][0] = *(const uint32_t*)&Ahi[r0 * APITCH + c0];
                ah[mi][1] = *(const uint32_t*)&Ahi[(r0 + 8) * APITCH + c0];
                ah[mi][2] = *(const uint32_t*)&Ahi[r0 * APITCH + c0 + 8];
                ah[mi][3] = *(const uint32_t*)&Ahi[(r0 + 8) * APITCH + c0 + 8];
                al[mi][0] = *(const uint32_t*)&Alo[r0 * APITCH + c0];
                al[mi][1] = *(const uint32_t*)&Alo[(r0 + 8) * APITCH + c0];
                al[mi][2] = *(const uint32_t*)&Alo[r0 * APITCH + c0 + 8];
                al[mi][3] = *(const uint32_t*)&Alo[(r0 + 8) * APITCH + c0 + 8];
            }
#pragma unroll
            for (int ni = 0; ni < 8; ni++) {
                const int n = wn * 64 + ni * 8 + g;
                uint32_t bh[2], bl[2];
                bh[0] = *(const uint32_t*)&Bhi[n * APITCH + c0];
                bh[1] = *(const uint32_t*)&Bhi[n * APITCH + c0 + 8];
                bl[0] = *(const uint32_t*)&Blo[n * APITCH + c0];
                bl[1] = *(const uint32_t*)&Blo[n * APITCH + c0 + 8];
#pragma unroll
                for (int mi = 0; mi < 2; mi++) {
                    mma16816(acc[mi][ni], ah[mi], bh, acc[mi][ni]);
                    mma16816(acc[mi][ni], al[mi], bh, acc[mi][ni]);
                    mma16816(acc[mi][ni], ah[mi], bl, acc[mi][ni]);
                }
            }
        }
        __syncthreads();
    }

#pragma unroll
    for (int mi = 0; mi < 2; mi++) {
        const int r0 = mtile * 128 + wm * 32 + mi * 16 + g;
#pragma unroll
        for (int ni = 0; ni < 8; ni++) {
            const int cl = wn * 64 + ni * 8 + tg * 2;
            const int cgl = ntile * 128 + cl;
            float b0 = bias_sm[cl], b1 = bias_sm[cl + 1];
            float2 o0 = make_float2(acc[mi][ni][0] + b0, acc[mi][ni][1] + b1);
            float2 o1 = make_float2(acc[mi][ni][2] + b0, acc[mi][ni][3] + b1);
            *(float2*)(g_XP + ((long)ic * 16384 + r0) * 256 + cgl) = o0;
            *(float2*)(g_XP + ((long)ic * 16384 + r0 + 8) * 256 + cgl) = o1;
        }
    }
}

// ---------------- K2a: per-head src/dst scores ----------------
__global__ __launch_bounds__(256) void k_scores(const float* __restrict__ att_src,
                                                const float* __restrict__ att_dst) {
    const int s = blockIdx.x, b = blockIdx.y, ic = blockIdx.z;
    const int tid = threadIdx.x;
    const int lane = tid & 31, w = tid >> 5;

    float v = g_XP[((long)(ic * 64 + b) * 256 + s) * 256 + tid];
    float ps = v * att_src[ic * 256 + tid];
    float pd = v * att_dst[ic * 256 + tid];
#pragma unroll
    for (int o = 16; o; o >>= 1) {
        ps += __shfl_xor_sync(0xffffffffu, ps, o);
        pd += __shfl_xor_sync(0xffffffffu, pd, o);
    }
    if (lane == 0) {
        long base = ((long)(ic * 64 + b) * 256 + s) * 8 + w;
        g_AS[base] = ps;
        g_AD[base] = pd;
    }
}

// ---------------- K2b: packed adjacency masks ----------------
__global__ __launch_bounds__(256) void k_masks(const int* __restrict__ A) {
    const int s = blockIdx.x, i = blockIdx.y, b = blockIdx.z;
    const int t = threadIdx.x;
    const int lane = t & 31, w = t >> 5;
    int v = A[((long)((b * 2 + i) * 256 + s)) * 256 + t];
    unsigned m1 = __ballot_sync(0xffffffffu, (v == 2) | (v == 4));
    unsigned m2 = __ballot_sync(0xffffffffu, (v == 3) | (v == 4));
    if (lane == 0) {
        long base = ((long)((b * 2 + i) * 256 + s)) * 8 + w;
        g_M1[base] = m1;
        g_M2[base] = m2;
    }
}

// ---------------- K3: HMMA masked-softmax attention ----------------
// grid (8 h, 2 i, 64 b), 256 threads (8 warps). Per conv:
//   out[t][d] = sum_s P[s][t] * V[s][d]; M=256 (t, 32 rows/warp), N=32 (d), K=256 (s),
//   K chunked by 32. P generated as bf16x2 hi/lo words, s-major layout P[sp][t].
//   Softmax shift m_t = max(0, lrelu(maxAS + ad_t)) >= true masked max (monotonicity).
// dynamic smem layout (words/floats):
#define PW 264                       // P word pitch over t (256 + 8 pad)
#define VW 132                       // V word pitch over s-pairs (128 + 4 pad)
#define SM_MSK   0                   // unsigned[256*8]           8192 B
#define SM_PHI   (8192)              // uint32[16*PW]             16896 B
#define SM_PLO   (SM_PHI + 16*PW*4)
#define SM_VHI   (SM_PLO + 16*PW*4)  // uint32[32*VW]             16896 B
#define SM_VLO   (SM_VHI + 32*VW*4)
#define SM_AS    (SM_VLO + 32*VW*4)  // float[256]
#define SM_AD    (SM_AS + 1024)
#define SM_DINV  (SM_AD + 1024)
#define SM_RED   (SM_DINV + 1024)    // float[8]
#define ATTN_SMEM (SM_RED + 32)

__global__ __launch_bounds__(256) void k_attn_mma(const float* __restrict__ gbias) {
    extern __shared__ char sm_[];
    unsigned* msk  = (unsigned*)(sm_ + SM_MSK);
    uint32_t* Phi  = (uint32_t*)(sm_ + SM_PHI);
    uint32_t* Plo  = (uint32_t*)(sm_ + SM_PLO);
    uint32_t* Vhi  = (uint32_t*)(sm_ + SM_VHI);
    uint32_t* Vlo  = (uint32_t*)(sm_ + SM_VLO);
    float* as_sm   = (float*)(sm_ + SM_AS);
    float* ad_sm   = (float*)(sm_ + SM_AD);
    float* dinv_sm = (float*)(sm_ + SM_DINV);
    float* red_sm  = (float*)(sm_ + SM_RED);

    const int h = blockIdx.x, i = blockIdx.y, b = blockIdx.z;
    const int tid = threadIdx.x, lane = tid & 31, w = tid >> 5;
    const int g = lane >> 2, tg = lane & 3;

    float accP[2][4][4];
#pragma unroll
    for (int mi = 0; mi < 2; mi++)
#pragma unroll
        for (int ni = 0; ni < 4; ni++)
#pragma unroll
            for (int q = 0; q < 4; q++) accP[mi][ni][q] = 0.f;

    for (int c = 0; c < 2; c++) {
        const int ic = i * 2 + c;
        const long xpbase = ((long)(ic * 64 + b) * 256) * 256;
        __syncthreads();   // protect smem from previous conv's readers

        // ---- load mask + scores; block-reduce maxAS ----
        {
            const unsigned* gm = (c == 0 ? g_M1 : g_M2) + ((long)((b * 2 + i) * 256)) * 8;
#pragma unroll
            for (int j = 0; j < 8; j++) msk[tid + 256 * j] = gm[tid + 256 * j];
            long sbase = ((long)(ic * 64 + b) * 256 + tid) * 8 + h;
            float av = g_AS[sbase];
            as_sm[tid] = av;
            ad_sm[tid] = g_AD[sbase];
            float mv = av;
#pragma unroll
            for (int o = 16; o; o >>= 1) mv = fmaxf(mv, __shfl_xor_sync(0xffffffffu, mv, o));
            if (lane == 0) red_sm[w] = mv;
        }
        // ---- V staging: Vt[d][s-pair] bf16x2 hi/lo (threads 0..127) ----
        if (tid < 128) {
            const float* r0p = g_XP + xpbase + (long)(2 * tid) * 256 + h * 32;
            const float* r1p = r0p + 256;
#pragma unroll
            for (int j = 0; j < 8; j++) {
                float4 f0 = *(const float4*)(r0p + j * 4);
                float4 f1 = *(const float4*)(r1p + j * 4);
                uint32_t hw, lw;
                split2(f0.x, f1.x, hw, lw);
                Vhi[(j * 4 + 0) * VW + tid] = hw; Vlo[(j * 4 + 0) * VW + tid] = lw;
                split2(f0.y, f1.y, hw, lw);
                Vhi[(j * 4 + 1) * VW + tid] = hw; Vlo[(j * 4 + 1) * VW + tid] = lw;
                split2(f0.z, f1.z, hw, lw);
                Vhi[(j * 4 + 2) * VW + tid] = hw; Vlo[(j * 4 + 2) * VW + tid] = lw;
                split2(f0.w, f1.w, hw, lw);
                Vhi[(j * 4 + 3) * VW + tid] = hw; Vlo[(j * 4 + 3) * VW + tid] = lw;
            }
        }
        __syncthreads();

        float mAS = red_sm[0];
#pragma unroll
        for (int j = 1; j < 8; j++) mAS = fmaxf(mAS, red_sm[j]);
        const float ad = ad_sm[tid];
        float rawm = mAS + ad;
        const float mt = fmaxf(0.f, fmaxf(rawm, 0.2f * rawm));

        float dloc = 0.f;
        float acc[2][4][4];
#pragma unroll
        for (int mi = 0; mi < 2; mi++)
#pragma unroll
            for (int ni = 0; ni < 4; ni++)
#pragma unroll
                for (int q = 0; q < 4; q++) acc[mi][ni][q] = 0.f;

        for (int ch = 0; ch < 8; ch++) {
            const int s0 = ch * 32;
            // ---- P chunk generation: thread owns dest column t=tid ----
#pragma unroll
            for (int sp = 0; sp < 16; sp++) {
                int sA = s0 + sp * 2;
                unsigned bA = (msk[sA * 8 + w] >> lane) & 1u;
                unsigned bB = (msk[(sA + 1) * 8 + w] >> lane) & 1u;
                float rA = as_sm[sA] + ad, rB = as_sm[sA + 1] + ad;
                float lA = bA ? fmaxf(rA, 0.2f * rA) : 0.f;
                float lB = bB ? fmaxf(rB, 0.2f * rB) : 0.f;
                float eA = __expf(lA - mt), eB = __expf(lB - mt);
                dloc += eA + eB;
                uint32_t hw, lw;
                split2(eA, eB, hw, lw);
                Phi[sp * PW + tid] = hw;
                Plo[sp * PW + tid] = lw;
            }
            __syncthreads();
            // ---- MMA: warp w owns t-rows [32w, 32w+32) ----
            const int c2 = s0 >> 1;
#pragma unroll
            for (int ka = 0; ka < 2; ka++) {
                const int spb = ka * 8 + tg;
                uint32_t ah[2][4], al[2][4];
#pragma unroll
                for (int mi = 0; mi < 2; mi++) {
                    const int r0 = w * 32 + mi * 16 + g;
                    ah[mi][0] = Phi[spb * PW + r0];
                    ah[mi][1] = Phi[spb * PW + r0 + 8];
                    ah[mi][2] = Phi[(spb + 4) * PW + r0];
                    ah[mi][3] = Phi[(spb + 4) * PW + r0 + 8];
                    al[mi][0] = Plo[spb * PW + r0];
                    al[mi][1] = Plo[spb * PW + r0 + 8];
                    al[mi][2] = Plo[(spb + 4) * PW + r0];
                    al[mi][3] = Plo[(spb + 4) * PW + r0 + 8];
                }
#pragma unroll
                for (int ni = 0; ni < 4; ni++) {
                    const int n = ni * 8 + g;
                    uint32_t bh[2], bl[2];
                    bh[0] = Vhi[n * VW + c2 + ka * 8 + tg];
                    bh[1] = Vhi[n * VW + c2 + ka * 8 + tg + 4];
                    bl[0] = Vlo[n * VW + c2 + ka * 8 + tg];
                    bl[1] = Vlo[n * VW + c2 + ka * 8 + tg + 4];
#pragma unroll
                    for (int mi = 0; mi < 2; mi++) {
                        mma16816(acc[mi][ni], ah[mi], bh, acc[mi][ni]);
                        mma16816(acc[mi][ni], al[mi], bh, acc[mi][ni]);
                        mma16816(acc[mi][ni], ah[mi], bl, acc[mi][ni]);
                    }
                }
            }
            __syncthreads();
        }

        // ---- epilogue: accP += acc/denom + xproj + gbias ----
        dinv_sm[tid] = 1.f / dloc;
        __syncthreads();

#pragma unroll
        for (int ni = 0; ni < 4; ni++) {
            const int col = h * 32 + ni * 8 + tg * 2;
            const float gb0 = gbias[ic * 256 + col];
            const float gb1 = gbias[ic * 256 + col + 1];
#pragma unroll
            for (int mi = 0; mi < 2; mi++) {
                const int r0 = w * 32 + mi * 16 + g;
                const float di0 = dinv_sm[r0], di1 = dinv_sm[r0 + 8];
                const float* xp0 = g_XP + xpbase + (long)r0 * 256 + col;
                float2 x0 = *(const float2*)xp0;
                float2 x1 = *(const float2*)(xp0 + 8 * 256);
                accP[mi][ni][0] += acc[mi][ni][0] * di0 + x0.x + gb0;
                accP[mi][ni][1] += acc[mi][ni][1] * di0 + x0.y + gb1;
                accP[mi][ni][2] += acc[mi][ni][2] * di1 + x1.x + gb0;
                accP[mi][ni][3] += acc[mi][ni][3] * di1 + x1.y + gb1;
            }
        }
    }

    // ---- write H[b][i][t][col] ----
#pragma unroll
    for (int mi = 0; mi < 2; mi++) {
        const int t0 = w * 32 + mi * 16 + g;
#pragma unroll
        for (int ni = 0; ni < 4; ni++) {
            const int col = h * 32 + ni * 8 + tg * 2;
            float* d0 = g_H + ((long)((b * 2 + i) * 256 + t0)) * 256 + col;
            *(float2*)d0 = make_float2(accP[mi][ni][0], accP[mi][ni][1]);
            *(float2*)(d0 + 8 * 256) = make_float2(accP[mi][ni][2], accP[mi][ni][3]);
        }
    }
}

// ---------------- K4: cross-order mean + PReLU ----------------
__global__ __launch_bounds__(256) void k_final(const float* __restrict__ prelu_a,
                                               float* __restrict__ out) {
    int idx = blockIdx.x * 256 + threadIdx.x;
    int d = idx & 255;
    int t = (idx >> 8) & 255;
    int b = idx >> 16;
    long i0 = ((long)((b * 2 + 0) * 256 + t)) * 256 + d;
    long i1 = ((long)((b * 2 + 1) * 256 + t)) * 256 + d;
    float h0 = g_H[i0], h1 = g_H[i1];
    float mn = 0.5f * (h0 + h1);
    float a = prelu_a[d];
    float o0 = h0 + mn, o1 = h1 + mn;
    out[i0] = (o0 >= 0.f) ? o0 : a * o0;
    out[i1] = (o1 >= 0.f) ? o1 : a * o1;
}

// ---------------- launch ----------------
extern "C" void kernel_launch(void* const* d_in, const int* in_sizes, int n_in,
                              void* d_out, int out_size) {
    const float* x        = (const float*)d_in[0];
    const int*   A        = (const int*)d_in[1];
    const float* Wp       = (const float*)d_in[2];
    const float* bp       = (const float*)d_in[3];
    const float* att_src  = (const float*)d_in[4];
    const float* att_dst  = (const float*)d_in[5];
    const float* gbias    = (const float*)d_in[6];
    const float* prelu_a  = (const float*)d_in[7];
    float* out = (float*)d_out;

    cudaFuncSetAttribute(k_attn_mma, cudaFuncAttributeMaxDynamicSharedMemorySize, ATTN_SMEM);

    k_proj_mma<<<dim3(2, 128, 4), 256>>>(x, Wp, bp);
    k_scores  <<<dim3(256, 64, 4), 256>>>(att_src, att_dst);
    k_masks   <<<dim3(256, 2, 64), 256>>>(A);
    k_attn_mma<<<dim3(8, 2, 64), 256, ATTN_SMEM>>>(gbias);
    k_final   <<<16384, 256>>>(prelu_a, out);
}

// round 13
// speedup vs baseline: 1.6701x; 1.1840x over previous
#include <cuda_runtime.h>
#include <cuda_bf16.h>
#include <cstdint>
#include <math.h>

// Problem constants
#define NB   64
#define ORD  2
#define SS   256
#define DD   256
#define NH   8
#define HDH  32   // head dim

// ---------------- scratch (device globals: allocation-free) ----------------
__device__ float g_XP[4L * NB * SS * DD];          // XP[ic][row][d]
__device__ float g_H[(long)NB * ORD * SS * DD];
__device__ float g_AS[4 * NB * SS * NH];
__device__ float g_AD[4 * NB * SS * NH];
__device__ unsigned g_M1[NB * ORD * SS * (SS / 32)];
__device__ unsigned g_M2[NB * ORD * SS * (SS / 32)];

// ---------------- mma.sync helpers (portable sm_80+ PTX; safe on compute_103) ----
__device__ __forceinline__ void mma16816(float* d, const uint32_t* a,
                                         const uint32_t* b, const float* c) {
    asm volatile(
        "mma.sync.aligned.m16n8k16.row.col.f32.bf16.bf16.f32 "
        "{%0,%1,%2,%3}, {%4,%5,%6,%7}, {%8,%9}, {%10,%11,%12,%13};"
        : "=f"(d[0]), "=f"(d[1]), "=f"(d[2]), "=f"(d[3])
        : "r"(a[0]), "r"(a[1]), "r"(a[2]), "r"(a[3]),
          "r"(b[0]), "r"(b[1]),
          "f"(c[0]), "f"(c[1]), "f"(c[2]), "f"(c[3]));
}

__device__ __forceinline__ void split2(float a, float b, uint32_t& h, uint32_t& l) {
    __nv_bfloat162 hb = __floats2bfloat162_rn(a, b);
    float ra = a - __bfloat162float(hb.x);
    float rb = b - __bfloat162float(hb.y);
    __nv_bfloat162 lb = __floats2bfloat162_rn(ra, rb);
    h = *reinterpret_cast<uint32_t*>(&hb);
    l = *reinterpret_cast<uint32_t*>(&lb);
}

// ---------------- K1: mma.sync split-bf16 projection GEMM ----------------
#define APITCH 40   // bf16 elements per smem row (32 data + 8 pad)
__global__ __launch_bounds__(256) void k_proj_mma(const float* __restrict__ x,
                                                  const float* __restrict__ Wp,
                                                  const float* __restrict__ bp) {
    __shared__ uint16_t Ahi[128 * APITCH];
    __shared__ uint16_t Alo[128 * APITCH];
    __shared__ uint16_t Bhi[128 * APITCH];
    __shared__ uint16_t Blo[128 * APITCH];
    __shared__ float    bias_sm[128];

    const int tid = threadIdx.x;
    const int lane = tid & 31, wid = tid >> 5;
    const int wm = wid & 3, wn = wid >> 2;
    const int g = lane >> 2, tg = lane & 3;

    const int ntile = blockIdx.x;
    const int mtile = blockIdx.y;
    const int ic = blockIdx.z, i = ic >> 1;

    const int sr = tid >> 1;
    const int kh = (tid & 1) * 16;

    if (tid < 128) bias_sm[tid] = bp[ic * 256 + ntile * 128 + tid];

    const int grow = mtile * 128 + sr;
    const int gb_ = grow >> 8, gs = grow & 255;
    const float* arow = x + ((long)((gb_ * 2 + i) * 256 + gs)) * 256;
    const int ncol = ntile * 128 + sr;
    const float* wcolbase = Wp + (long)ic * 65536 + ncol;

    float acc[2][8][4];
#pragma unroll
    for (int mi = 0; mi < 2; mi++)
#pragma unroll
        for (int ni = 0; ni < 8; ni++)
#pragma unroll
            for (int q = 0; q < 4; q++) acc[mi][ni][q] = 0.f;

    for (int k0 = 0; k0 < 256; k0 += 32) {
        {
            float4 f0 = *(const float4*)(arow + k0 + kh);
            float4 f1 = *(const float4*)(arow + k0 + kh + 4);
            float4 f2 = *(const float4*)(arow + k0 + kh + 8);
            float4 f3 = *(const float4*)(arow + k0 + kh + 12);
            uint4 h0, l0, h1, l1;
            split2(f0.x, f0.y, h0.x, l0.x); split2(f0.z, f0.w, h0.y, l0.y);
            split2(f1.x, f1.y, h0.z, l0.z); split2(f1.z, f1.w, h0.w, l0.w);
            split2(f2.x, f2.y, h1.x, l1.x); split2(f2.z, f2.w, h1.y, l1.y);
            split2(f3.x, f3.y, h1.z, l1.z); split2(f3.z, f3.w, h1.w, l1.w);
            uint16_t* pa = &Ahi[sr * APITCH + kh];
            uint16_t* pl = &Alo[sr * APITCH + kh];
            *(uint4*)(pa) = h0; *(uint4*)(pa + 8) = h1;
            *(uint4*)(pl) = l0; *(uint4*)(pl + 8) = l1;
        }
        {
            float f[16];
#pragma unroll
            for (int t = 0; t < 16; t++) f[t] = wcolbase[(long)(k0 + kh + t) * 256];
            uint4 h0, l0, h1, l1;
            split2(f[0], f[1], h0.x, l0.x);  split2(f[2], f[3], h0.y, l0.y);
            split2(f[4], f[5], h0.z, l0.z);  split2(f[6], f[7], h0.w, l0.w);
            split2(f[8], f[9], h1.x, l1.x);  split2(f[10], f[11], h1.y, l1.y);
            split2(f[12], f[13], h1.z, l1.z); split2(f[14], f[15], h1.w, l1.w);
            uint16_t* pb = &Bhi[sr * APITCH + kh];
            uint16_t* pl = &Blo[sr * APITCH + kh];
            *(uint4*)(pb) = h0; *(uint4*)(pb + 8) = h1;
            *(uint4*)(pl) = l0; *(uint4*)(pl + 8) = l1;
        }
        __syncthreads();

#pragma unroll
        for (int ka = 0; ka < 32; ka += 16) {
            uint32_t ah[2][4], al[2][4];
            const int c0 = ka + tg * 2;
#pragma unroll
            for (int mi = 0; mi < 2; mi++) {
                const int r0 = wm * 32 + mi * 16 + g;
                ah[mi][0] = *(const uint32_t*)&Ahi[r0 * APITCH + c0];
                ah[mi][1] = *(const uint32_t*)&Ahi[(r0 + 8) * APITCH + c0];
                ah[mi][2] = *(const uint32_t*)&Ahi[r0 * APITCH + c0 + 8];
                ah[mi][3] = *(const uint32_t*)&Ahi[(r0 + 8) * APITCH + c0 + 8];
                al[mi][0] = *(const uint32_t*)&Alo[r0 * APITCH + c0];
                al[mi][1] = *(const uint32_t*)&Alo[(r0 + 8) * APITCH + c0];
                al[mi][2] = *(const uint32_t*)&Alo[r0 * APITCH + c0 + 8];
                al[mi][3] = *(const uint32_t*)&Alo[(r0 + 8) * APITCH + c0 + 8];
            }
#pragma unroll
            for (int ni = 0; ni < 8; ni++) {
                const int n = wn * 64 + ni * 8 + g;
                uint32_t bh[2], bl[2];
                bh[0] = *(const uint32_t*)&Bhi[n * APITCH + c0];
                bh[1] = *(const uint32_t*)&Bhi[n * APITCH + c0 + 8];
                bl[0] = *(const uint32_t*)&Blo[n * APITCH + c0];
                bl[1] = *(const uint32_t*)&Blo[n * APITCH + c0 + 8];
#pragma unroll
                for (int mi = 0; mi < 2; mi++) {
                    mma16816(acc[mi][ni], ah[mi], bh, acc[mi][ni]);
                    mma16816(acc[mi][ni], al[mi], bh, acc[mi][ni]);
                    mma16816(acc[mi][ni], ah[mi], bl, acc[mi][ni]);
                }
            }
        }
        __syncthreads();
    }

#pragma unroll
    for (int mi = 0; mi < 2; mi++) {
        const int r0 = mtile * 128 + wm * 32 + mi * 16 + g;
#pragma unroll
        for (int ni = 0; ni < 8; ni++) {
            const int cl = wn * 64 + ni * 8 + tg * 2;
            const int cgl = ntile * 128 + cl;
            float b0 = bias_sm[cl], b1 = bias_sm[cl + 1];
            float2 o0 = make_float2(acc[mi][ni][0] + b0, acc[mi][ni][1] + b1);
            float2 o1 = make_float2(acc[mi][ni][2] + b0, acc[mi][ni][3] + b1);
            *(float2*)(g_XP + ((long)ic * 16384 + r0) * 256 + cgl) = o0;
            *(float2*)(g_XP + ((long)ic * 16384 + r0 + 8) * 256 + cgl) = o1;
        }
    }
}

// ---------------- K2a: per-head src/dst scores ----------------
__global__ __launch_bounds__(256) void k_scores(const float* __restrict__ att_src,
                                                const float* __restrict__ att_dst) {
    const int s = blockIdx.x, b = blockIdx.y, ic = blockIdx.z;
    const int tid = threadIdx.x;
    const int lane = tid & 31, w = tid >> 5;

    float v = g_XP[((long)(ic * 64 + b) * 256 + s) * 256 + tid];
    float ps = v * att_src[ic * 256 + tid];
    float pd = v * att_dst[ic * 256 + tid];
#pragma unroll
    for (int o = 16; o; o >>= 1) {
        ps += __shfl_xor_sync(0xffffffffu, ps, o);
        pd += __shfl_xor_sync(0xffffffffu, pd, o);
    }
    if (lane == 0) {
        long base = ((long)(ic * 64 + b) * 256 + s) * 8 + w;
        g_AS[base] = ps;
        g_AD[base] = pd;
    }
}

// ---------------- K2b: packed adjacency masks ----------------
__global__ __launch_bounds__(256) void k_masks(const int* __restrict__ A) {
    const int s = blockIdx.x, i = blockIdx.y, b = blockIdx.z;
    const int t = threadIdx.x;
    const int lane = t & 31, w = t >> 5;
    int v = A[((long)((b * 2 + i) * 256 + s)) * 256 + t];
    unsigned m1 = __ballot_sync(0xffffffffu, (v == 2) | (v == 4));
    unsigned m2 = __ballot_sync(0xffffffffu, (v == 3) | (v == 4));
    if (lane == 0) {
        long base = ((long)((b * 2 + i) * 256 + s)) * 8 + w;
        g_M1[base] = m1;
        g_M2[base] = m2;
    }
}

// ---------------- K3: HMMA masked-softmax attention ----------------
// grid (8 h, 2 i, 64 b), 256 threads (8 warps), 2 CTAs/SM.
// P-generation is exp-free in the hot loop via lrelu-branch factorization:
//   P[s][t] = !edge        -> exp(-mt)
//             edge, r >= 0 -> exp(as[s]) * exp(ad[t]-mt)
//             edge, r <  0 -> exp(.2 as[s]) * exp(.2 ad[t]-mt)
//   with r = as[s]+ad[t], mt = max(0, lrelu(maxAS + ad[t])) >= true masked max.
#define PW 264                       // P word pitch over t (256 + 8 pad)
#define VW 132                       // V word pitch over s-pairs (128 + 4 pad)
#define SM_MSK   0                   // unsigned[256*8]           8192 B
#define SM_PHI   (8192)              // uint32[16*PW]
#define SM_PLO   (SM_PHI + 16*PW*4)
#define SM_VHI   (SM_PLO + 16*PW*4)  // uint32[32*VW]
#define SM_VLO   (SM_VHI + 32*VW*4)
#define SM_AS    (SM_VLO + 32*VW*4)  // float[256]
#define SM_EAS   (SM_AS + 1024)      // float[256] exp(as)
#define SM_EAS2  (SM_EAS + 1024)     // float[256] exp(.2 as)
#define SM_AD    (SM_EAS2 + 1024)
#define SM_DINV  (SM_AD + 1024)
#define SM_RED   (SM_DINV + 1024)    // float[8]
#define ATTN_SMEM (SM_RED + 32)

__global__ __launch_bounds__(256, 2) void k_attn_mma(const float* __restrict__ gbias) {
    extern __shared__ char sm_[];
    unsigned* msk  = (unsigned*)(sm_ + SM_MSK);
    uint32_t* Phi  = (uint32_t*)(sm_ + SM_PHI);
    uint32_t* Plo  = (uint32_t*)(sm_ + SM_PLO);
    uint32_t* Vhi  = (uint32_t*)(sm_ + SM_VHI);
    uint32_t* Vlo  = (uint32_t*)(sm_ + SM_VLO);
    float* as_sm   = (float*)(sm_ + SM_AS);
    float* eas_sm  = (float*)(sm_ + SM_EAS);
    float* eas2_sm = (float*)(sm_ + SM_EAS2);
    float* ad_sm   = (float*)(sm_ + SM_AD);
    float* dinv_sm = (float*)(sm_ + SM_DINV);
    float* red_sm  = (float*)(sm_ + SM_RED);

    const int h = blockIdx.x, i = blockIdx.y, b = blockIdx.z;
    const int tid = threadIdx.x, lane = tid & 31, w = tid >> 5;
    const int g = lane >> 2, tg = lane & 3;

    float accP[2][4][4];
#pragma unroll
    for (int mi = 0; mi < 2; mi++)
#pragma unroll
        for (int ni = 0; ni < 4; ni++)
#pragma unroll
            for (int q = 0; q < 4; q++) accP[mi][ni][q] = 0.f;

    for (int c = 0; c < 2; c++) {
        const int ic = i * 2 + c;
        const long xpbase = ((long)(ic * 64 + b) * 256) * 256;
        __syncthreads();   // protect smem from previous conv's readers

        // ---- load mask + scores; per-s exp tables; block-reduce maxAS ----
        {
            const unsigned* gm = (c == 0 ? g_M1 : g_M2) + ((long)((b * 2 + i) * 256)) * 8;
#pragma unroll
            for (int j = 0; j < 8; j++) msk[tid + 256 * j] = gm[tid + 256 * j];
            long sbase = ((long)(ic * 64 + b) * 256 + tid) * 8 + h;
            float av = g_AS[sbase];
            as_sm[tid]   = av;
            eas_sm[tid]  = __expf(av);
            eas2_sm[tid] = __expf(0.2f * av);
            ad_sm[tid] = g_AD[sbase];
            float mv = av;
#pragma unroll
            for (int o = 16; o; o >>= 1) mv = fmaxf(mv, __shfl_xor_sync(0xffffffffu, mv, o));
            if (lane == 0) red_sm[w] = mv;
        }
        // ---- V staging: Vt[d][s-pair] bf16x2 hi/lo (threads 0..127) ----
        if (tid < 128) {
            const float* r0p = g_XP + xpbase + (long)(2 * tid) * 256 + h * 32;
            const float* r1p = r0p + 256;
#pragma unroll
            for (int j = 0; j < 8; j++) {
                float4 f0 = *(const float4*)(r0p + j * 4);
                float4 f1 = *(const float4*)(r1p + j * 4);
                uint32_t hw, lw;
                split2(f0.x, f1.x, hw, lw);
                Vhi[(j * 4 + 0) * VW + tid] = hw; Vlo[(j * 4 + 0) * VW + tid] = lw;
                split2(f0.y, f1.y, hw, lw);
                Vhi[(j * 4 + 1) * VW + tid] = hw; Vlo[(j * 4 + 1) * VW + tid] = lw;
                split2(f0.z, f1.z, hw, lw);
                Vhi[(j * 4 + 2) * VW + tid] = hw; Vlo[(j * 4 + 2) * VW + tid] = lw;
                split2(f0.w, f1.w, hw, lw);
                Vhi[(j * 4 + 3) * VW + tid] = hw; Vlo[(j * 4 + 3) * VW + tid] = lw;
            }
        }
        __syncthreads();

        float mAS = red_sm[0];
#pragma unroll
        for (int j = 1; j < 8; j++) mAS = fmaxf(mAS, red_sm[j]);
        const float ad = ad_sm[tid];
        float rawm = mAS + ad;
        const float mt = fmaxf(0.f, fmaxf(rawm, 0.2f * rawm));
        // per-thread factors (3 exps per conv)
        const float e0t = __expf(ad - mt);          // unmasked, r >= 0
        const float e1t = __expf(0.2f * ad - mt);   // unmasked, r <  0
        const float emt = __expf(-mt);              // masked (logit 0)

        float dloc = 0.f;
        float acc[2][4][4];
#pragma unroll
        for (int mi = 0; mi < 2; mi++)
#pragma unroll
            for (int ni = 0; ni < 4; ni++)
#pragma unroll
                for (int q = 0; q < 4; q++) acc[mi][ni][q] = 0.f;

        for (int ch = 0; ch < 8; ch++) {
            const int s0 = ch * 32;
            // ---- P chunk generation (exp-free): thread owns dest column t=tid ----
#pragma unroll
            for (int sp = 0; sp < 16; sp++) {
                int sA = s0 + sp * 2;
                unsigned bA = (msk[sA * 8 + w] >> lane) & 1u;
                unsigned bB = (msk[(sA + 1) * 8 + w] >> lane) & 1u;
                float pA = (as_sm[sA] + ad >= 0.f) ? eas_sm[sA] * e0t : eas2_sm[sA] * e1t;
                float pB = (as_sm[sA + 1] + ad >= 0.f) ? eas_sm[sA + 1] * e0t : eas2_sm[sA + 1] * e1t;
                pA = bA ? pA : emt;
                pB = bB ? pB : emt;
                dloc += pA + pB;
                uint32_t hw, lw;
                split2(pA, pB, hw, lw);
                Phi[sp * PW + tid] = hw;
                Plo[sp * PW + tid] = lw;
            }
            __syncthreads();
            // ---- MMA: warp w owns t-rows [32w, 32w+32) ----
            const int c2 = s0 >> 1;
#pragma unroll
            for (int ka = 0; ka < 2; ka++) {
                const int spb = ka * 8 + tg;
                uint32_t ah[2][4], al[2][4];
#pragma unroll
                for (int mi = 0; mi < 2; mi++) {
                    const int r0 = w * 32 + mi * 16 + g;
                    ah[mi][0] = Phi[spb * PW + r0];
                    ah[mi][1] = Phi[spb * PW + r0 + 8];
                    ah[mi][2] = Phi[(spb + 4) * PW + r0];
                    ah[mi][3] = Phi[(spb + 4) * PW + r0 + 8];
                    al[mi][0] = Plo[spb * PW + r0];
                    al[mi][1] = Plo[spb * PW + r0 + 8];
                    al[mi][2] = Plo[(spb + 4) * PW + r0];
                    al[mi][3] = Plo[(spb + 4) * PW + r0 + 8];
                }
#pragma unroll
                for (int ni = 0; ni < 4; ni++) {
                    const int n = ni * 8 + g;
                    uint32_t bh[2], bl[2];
                    bh[0] = Vhi[n * VW + c2 + ka * 8 + tg];
                    bh[1] = Vhi[n * VW + c2 + ka * 8 + tg + 4];
                    bl[0] = Vlo[n * VW + c2 + ka * 8 + tg];
                    bl[1] = Vlo[n * VW + c2 + ka * 8 + tg + 4];
#pragma unroll
                    for (int mi = 0; mi < 2; mi++) {
                        mma16816(acc[mi][ni], ah[mi], bh, acc[mi][ni]);
                        mma16816(acc[mi][ni], al[mi], bh, acc[mi][ni]);
                        mma16816(acc[mi][ni], ah[mi], bl, acc[mi][ni]);
                    }
                }
            }
            __syncthreads();
        }

        // ---- epilogue: accP += acc/denom + xproj + gbias ----
        dinv_sm[tid] = 1.f / dloc;
        __syncthreads();

#pragma unroll
        for (int ni = 0; ni < 4; ni++) {
            const int col = h * 32 + ni * 8 + tg * 2;
            const float gb0 = gbias[ic * 256 + col];
            const float gb1 = gbias[ic * 256 + col + 1];
#pragma unroll
            for (int mi = 0; mi < 2; mi++) {
                const int r0 = w * 32 + mi * 16 + g;
                const float di0 = dinv_sm[r0], di1 = dinv_sm[r0 + 8];
                const float* xp0 = g_XP + xpbase + (long)r0 * 256 + col;
                float2 x0 = *(const float2*)xp0;
                float2 x1 = *(const float2*)(xp0 + 8 * 256);
                accP[mi][ni][0] += acc[mi][ni][0] * di0 + x0.x + gb0;
                accP[mi][ni][1] += acc[mi][ni][1] * di0 + x0.y + gb1;
                accP[mi][ni][2] += acc[mi][ni][2] * di1 + x1.x + gb0;
                accP[mi][ni][3] += acc[mi][ni][3] * di1 + x1.y + gb1;
            }
        }
    }

    // ---- write H[b][i][t][col] ----
#pragma unroll
    for (int mi = 0; mi < 2; mi++) {
        const int t0 = w * 32 + mi * 16 + g;
#pragma unroll
        for (int ni = 0; ni < 4; ni++) {
            const int col = h * 32 + ni * 8 + tg * 2;
            float* d0 = g_H + ((long)((b * 2 + i) * 256 + t0)) * 256 + col;
            *(float2*)d0 = make_float2(accP[mi][ni][0], accP[mi][ni][1]);
            *(float2*)(d0 + 8 * 256) = make_float2(accP[mi][ni][2], accP[mi][ni][3]);
        }
    }
}

// ---------------- K4: cross-order mean + PReLU ----------------
__global__ __launch_bounds__(256) void k_final(const float* __restrict__ prelu_a,
                                               float* __restrict__ out) {
    int idx = blockIdx.x * 256 + threadIdx.x;
    int d = idx & 255;
    int t = (idx >> 8) & 255;
    int b = idx >> 16;
    long i0 = ((long)((b * 2 + 0) * 256 + t)) * 256 + d;
    long i1 = ((long)((b * 2 + 1) * 256 + t)) * 256 + d;
    float h0 = g_H[i0], h1 = g_H[i1];
    float mn = 0.5f * (h0 + h1);
    float a = prelu_a[d];
    float o0 = h0 + mn, o1 = h1 + mn;
    out[i0] = (o0 >= 0.f) ? o0 : a * o0;
    out[i1] = (o1 >= 0.f) ? o1 : a * o1;
}

// ---------------- launch ----------------
extern "C" void kernel_launch(void* const* d_in, const int* in_sizes, int n_in,
                              void* d_out, int out_size) {
    const float* x        = (const float*)d_in[0];
    const int*   A        = (const int*)d_in[1];
    const float* Wp       = (const float*)d_in[2];
    const float* bp       = (const float*)d_in[3];
    const float* att_src  = (const float*)d_in[4];
    const float* att_dst  = (const float*)d_in[5];
    const float* gbias    = (const float*)d_in[6];
    const float* prelu_a  = (const float*)d_in[7];
    float* out = (float*)d_out;

    cudaFuncSetAttribute(k_attn_mma, cudaFuncAttributeMaxDynamicSharedMemorySize, ATTN_SMEM);

    k_proj_mma<<<dim3(2, 128, 4), 256>>>(x, Wp, bp);
    k_scores  <<<dim3(256, 64, 4), 256>>>(att_src, att_dst);
    k_masks   <<<dim3(256, 2, 64), 256>>>(A);
    k_attn_mma<<<dim3(8, 2, 64), 256, ATTN_SMEM>>>(gbias);
    k_final   <<<16384, 256>>>(prelu_a, out);
}